// round 10
// baseline (speedup 1.0000x reference)
#include <cuda_runtime.h>

// LIF neuron recurrence, fully parallel across B*N neurons, serial over T.
//   out[t]  = (mem > 1.0f) ? 1 : 0
//   mem     = (0.5f*mem + syn) * (1 - out[t])
//   syn     = in[t]
// inputs: [T=100, B=256, N=2048] fp32 contiguous; output same shape.
//
// R10: R6 winning structure (float4, 512x256, prefetch depth 1; 61.06us /
// 76.3% DRAM) + __ldcs on LOADS ONLY. R2 bundled ldcs+stcs and regressed;
// this isolates the load hint. Mechanism: the zero-reuse 210MB read stream
// pollutes L2 and evicts dirty output lines early, forcing premature
// writebacks; evict-first reads leave L2 capacity to the write stream
// (R3 evidence: ~50MB of dirty lines buffered in L2 at kernel end).
// Stores keep default write-back policy.

constexpr int T_STEPS = 100;

__global__ void __launch_bounds__(256) lif_kernel(
    const float4* __restrict__ in,
    float4* __restrict__ out,
    int n4)
{
    int i = blockIdx.x * blockDim.x + threadIdx.x;
    if (i >= n4) return;

    float4 mem = make_float4(0.f, 0.f, 0.f, 0.f);
    float4 syn = make_float4(0.f, 0.f, 0.f, 0.f);

    size_t idx = (size_t)i;
    const size_t stride = (size_t)n4;

    // Prologue: issue first load before entering the loop.
    float4 x = __ldcs(&in[idx]);

    #pragma unroll 5
    for (int t = 0; t < T_STEPS; ++t) {
        // Prefetch next input before this iteration's store.
        float4 x_next;
        if (t + 1 < T_STEPS)
            x_next = __ldcs(&in[idx + stride]);

        float4 o;
        o.x = (mem.x > 1.0f) ? 1.0f : 0.0f;
        o.y = (mem.y > 1.0f) ? 1.0f : 0.0f;
        o.z = (mem.z > 1.0f) ? 1.0f : 0.0f;
        o.w = (mem.w > 1.0f) ? 1.0f : 0.0f;

        out[idx] = o;   // default write-back store

        mem.x = (0.5f * mem.x + syn.x) * (1.0f - o.x);
        mem.y = (0.5f * mem.y + syn.y) * (1.0f - o.y);
        mem.z = (0.5f * mem.z + syn.z) * (1.0f - o.z);
        mem.w = (0.5f * mem.w + syn.w) * (1.0f - o.w);

        syn = x;
        x = x_next;
        idx += stride;
    }
}

extern "C" void kernel_launch(void* const* d_in, const int* in_sizes, int n_in,
                              void* d_out, int out_size)
{
    const float* in = (const float*)d_in[0];
    float* out = (float*)d_out;

    const int BN = in_sizes[0] / T_STEPS;  // 524288
    const int n4 = BN / 4;                 // 131072 float4 lanes

    const int threads = 256;
    const int blocks = (n4 + threads - 1) / threads;  // 512

    lif_kernel<<<blocks, threads>>>(
        (const float4*)in, (float4*)out, n4);
}

// round 11
// speedup vs baseline: 1.0111x; 1.0111x over previous
#include <cuda_runtime.h>

// LIF neuron recurrence, fully parallel across B*N neurons, serial over T.
//   out[t]  = (mem > 1.0f) ? 1 : 0
//   mem     = (0.5f*mem + syn) * (1 - out[t])
//   syn     = in[t]
// inputs: [T=100, B=256, N=2048] fp32 contiguous; output same shape.
//
// FINAL (= R6, best of 11 measured configs: 61.06us kernel / 68.06us dur /
// 76.3% DRAM / 6041 GB/s, rel_err 0.0). float4 per thread, 512 blocks x 256
// threads (27 warps/SM), software-pipelined prefetch depth 1: load x(t+1)
// before storing o(t) — 2 reads in flight across the store, LDG->syn
// dependency decoupled by one iteration.
//
// Roofline conclusion: ~6.0TB/s (75-76% of 8TB/s spec) is the achievable
// mixed read/write DRAM ceiling on this part. Invariant across vector width
// (64/128/256-bit), occupancy (13-54 warps/SM), all cache-hint combinations
// (__ldcs/__stcs each regressed or neutral), read/write burst batching
// (neutral), and prefetch depth (depth 2 regressed via predicated in-body
// loads + 3-deep register rotation). Traffic is fixed at 419.4MB -> the
// kernel is at the memory roofline; the residual gap to spec is DRAM
// controller overhead (turnaround/refresh), not addressable from the SM.

constexpr int T_STEPS = 100;

__global__ void __launch_bounds__(256) lif_kernel(
    const float4* __restrict__ in,
    float4* __restrict__ out,
    int n4)
{
    int i = blockIdx.x * blockDim.x + threadIdx.x;
    if (i >= n4) return;

    float4 mem = make_float4(0.f, 0.f, 0.f, 0.f);
    float4 syn = make_float4(0.f, 0.f, 0.f, 0.f);

    size_t idx = (size_t)i;
    const size_t stride = (size_t)n4;

    // Prologue: issue first load before entering the loop.
    float4 x = in[idx];

    #pragma unroll 5
    for (int t = 0; t < T_STEPS; ++t) {
        // Prefetch next input before this iteration's store.
        float4 x_next;
        if (t + 1 < T_STEPS)
            x_next = in[idx + stride];

        float4 o;
        o.x = (mem.x > 1.0f) ? 1.0f : 0.0f;
        o.y = (mem.y > 1.0f) ? 1.0f : 0.0f;
        o.z = (mem.z > 1.0f) ? 1.0f : 0.0f;
        o.w = (mem.w > 1.0f) ? 1.0f : 0.0f;

        out[idx] = o;

        mem.x = (0.5f * mem.x + syn.x) * (1.0f - o.x);
        mem.y = (0.5f * mem.y + syn.y) * (1.0f - o.y);
        mem.z = (0.5f * mem.z + syn.z) * (1.0f - o.z);
        mem.w = (0.5f * mem.w + syn.w) * (1.0f - o.w);

        syn = x;
        x = x_next;
        idx += stride;
    }
}

extern "C" void kernel_launch(void* const* d_in, const int* in_sizes, int n_in,
                              void* d_out, int out_size)
{
    const float* in = (const float*)d_in[0];
    float* out = (float*)d_out;

    const int BN = in_sizes[0] / T_STEPS;  // 524288
    const int n4 = BN / 4;                 // 131072 float4 lanes

    const int threads = 256;
    const int blocks = (n4 + threads - 1) / threads;  // 512

    lif_kernel<<<blocks, threads>>>(
        (const float4*)in, (float4*)out, n4);
}

// round 12
// speedup vs baseline: 1.0235x; 1.0122x over previous
#include <cuda_runtime.h>

// LIF neuron recurrence, fully parallel across B*N neurons, serial over T.
//   out[t]  = (mem > 1.0f) ? 1 : 0
//   mem     = (0.5f*mem + syn) * (1 - out[t])   ==  out[t] ? 0 : fma(0.5,mem,syn)
//   syn     = in[t]
// inputs: [T=100, B=256, N=2048] fp32 contiguous; output same shape.
//
// R12 (final polish on R6, the best of 12 measured configs: 61.06us kernel /
// 76.3% DRAM / 6041 GB/s). float4 per thread, 512 blocks x 256 threads
// (27 warps/SM), software-pipelined prefetch depth 1. This round converts the
// membrane update from (0.5*mem+syn)*(1-o) [FADD+FFMA+FMUL, 3-op chain] to a
// predicated select [FFMA+FSEL, 2-op chain] — bit-identical since o∈{0,1}.
//
// Roofline conclusion: ~6.0TB/s (75-76% of 8TB/s spec) is the achievable
// mixed read/write DRAM ceiling. Invariant across vector width (64/128/256b),
// occupancy (13-54 warps/SM), all cache-hint combos, burst batching, and
// prefetch depth. Traffic fixed at 419.4MB -> kernel is at the memory
// roofline; residual gap to spec is DRAM controller overhead.

constexpr int T_STEPS = 100;

__global__ void __launch_bounds__(256) lif_kernel(
    const float4* __restrict__ in,
    float4* __restrict__ out,
    int n4)
{
    int i = blockIdx.x * blockDim.x + threadIdx.x;
    if (i >= n4) return;

    float4 mem = make_float4(0.f, 0.f, 0.f, 0.f);
    float4 syn = make_float4(0.f, 0.f, 0.f, 0.f);

    size_t idx = (size_t)i;
    const size_t stride = (size_t)n4;

    // Prologue: issue first load before entering the loop.
    float4 x = in[idx];

    #pragma unroll 5
    for (int t = 0; t < T_STEPS; ++t) {
        // Prefetch next input before this iteration's store.
        float4 x_next;
        if (t + 1 < T_STEPS)
            x_next = in[idx + stride];

        bool px = mem.x > 1.0f;
        bool py = mem.y > 1.0f;
        bool pz = mem.z > 1.0f;
        bool pw = mem.w > 1.0f;

        float4 o;
        o.x = px ? 1.0f : 0.0f;
        o.y = py ? 1.0f : 0.0f;
        o.z = pz ? 1.0f : 0.0f;
        o.w = pw ? 1.0f : 0.0f;

        out[idx] = o;

        // Select-form update: spike -> reset to 0, else decay+integrate.
        mem.x = px ? 0.0f : fmaf(0.5f, mem.x, syn.x);
        mem.y = py ? 0.0f : fmaf(0.5f, mem.y, syn.y);
        mem.z = pz ? 0.0f : fmaf(0.5f, mem.z, syn.z);
        mem.w = pw ? 0.0f : fmaf(0.5f, mem.w, syn.w);

        syn = x;
        x = x_next;
        idx += stride;
    }
}

extern "C" void kernel_launch(void* const* d_in, const int* in_sizes, int n_in,
                              void* d_out, int out_size)
{
    const float* in = (const float*)d_in[0];
    float* out = (float*)d_out;

    const int BN = in_sizes[0] / T_STEPS;  // 524288
    const int n4 = BN / 4;                 // 131072 float4 lanes

    const int threads = 256;
    const int blocks = (n4 + threads - 1) / threads;  // 512

    lif_kernel<<<blocks, threads>>>(
        (const float4*)in, (float4*)out, n4);
}

// round 13
// speedup vs baseline: 1.0240x; 1.0005x over previous
#include <cuda_runtime.h>

// LIF neuron recurrence, fully parallel across B*N neurons, serial over T.
//   out[t]  = (mem > 1.0f) ? 1 : 0
//   mem     = (0.5f*mem + syn) * (1 - out[t])   ==  out[t] ? 0 : fma(0.5,mem,syn)
//   syn     = in[t]
// inputs: [T=100, B=256, N=2048] fp32 contiguous; output same shape.
//
// FINAL (= R12, best of 13 measured configs: 60.58us kernel / 68.10us dur /
// 76.9% DRAM / 6088 GB/s, rel_err 0.0).
//   - float4 per thread, 512 blocks x 256 threads (27 warps/SM)
//   - software-pipelined prefetch depth 1: load x(t+1) before storing o(t)
//   - select-form membrane update (FFMA+FSEL, 2-op post-compare chain;
//     bit-identical to (0.5*mem+syn)*(1-o) since o∈{0,1}) — measured
//     fma 7.9->3.9%, kernel 61.1->60.6us
//
// Roofline conclusion: ~6.0-6.1TB/s (76% of 8TB/s spec) is the achievable
// mixed read/write DRAM ceiling on this part. Invariant across vector width
// (64/128/256-bit), occupancy (13-54 warps/SM), all cache-hint combinations,
// read/write burst batching, and prefetch depth (depth 2 regressed).
// Traffic is fixed at 419.4MB -> this kernel is at the memory roofline;
// the residual gap to spec is DRAM controller overhead (turnaround/refresh),
// not addressable from the SM.

constexpr int T_STEPS = 100;

__global__ void __launch_bounds__(256) lif_kernel(
    const float4* __restrict__ in,
    float4* __restrict__ out,
    int n4)
{
    int i = blockIdx.x * blockDim.x + threadIdx.x;
    if (i >= n4) return;

    float4 mem = make_float4(0.f, 0.f, 0.f, 0.f);
    float4 syn = make_float4(0.f, 0.f, 0.f, 0.f);

    size_t idx = (size_t)i;
    const size_t stride = (size_t)n4;

    // Prologue: issue first load before entering the loop.
    float4 x = in[idx];

    #pragma unroll 5
    for (int t = 0; t < T_STEPS; ++t) {
        // Prefetch next input before this iteration's store.
        float4 x_next;
        if (t + 1 < T_STEPS)
            x_next = in[idx + stride];

        bool px = mem.x > 1.0f;
        bool py = mem.y > 1.0f;
        bool pz = mem.z > 1.0f;
        bool pw = mem.w > 1.0f;

        float4 o;
        o.x = px ? 1.0f : 0.0f;
        o.y = py ? 1.0f : 0.0f;
        o.z = pz ? 1.0f : 0.0f;
        o.w = pw ? 1.0f : 0.0f;

        out[idx] = o;

        // Select-form update: spike -> reset to 0, else decay+integrate.
        mem.x = px ? 0.0f : fmaf(0.5f, mem.x, syn.x);
        mem.y = py ? 0.0f : fmaf(0.5f, mem.y, syn.y);
        mem.z = pz ? 0.0f : fmaf(0.5f, mem.z, syn.z);
        mem.w = pw ? 0.0f : fmaf(0.5f, mem.w, syn.w);

        syn = x;
        x = x_next;
        idx += stride;
    }
}

extern "C" void kernel_launch(void* const* d_in, const int* in_sizes, int n_in,
                              void* d_out, int out_size)
{
    const float* in = (const float*)d_in[0];
    float* out = (float*)d_out;

    const int BN = in_sizes[0] / T_STEPS;  // 524288
    const int n4 = BN / 4;                 // 131072 float4 lanes

    const int threads = 256;
    const int blocks = (n4 + threads - 1) / threads;  // 512

    lif_kernel<<<blocks, threads>>>(
        (const float4*)in, (float4*)out, n4);
}